// round 2
// baseline (speedup 1.0000x reference)
#include <cuda_runtime.h>
#include <cuda_bf16.h>
#include <math_constants.h>

// Problem constants
#define B_   2
#define S_   2048
#define D_   1024
#define H_   16
#define DK_  64
#define EPS_ 0.1f
#define M_ROWS (B_ * S_)          // 4096
#define N_QKV  (3 * D_)           // 3072

// Scratch (allocation-free requirement -> __device__ globals)
__device__ float g_qkv[M_ROWS * N_QKV];     // [B,S,3,H,dk] flattened = [m][n]
__device__ float g_attn[M_ROWS * D_];       // [B,S,H,dk] = [B,S,D]

// ---------------------------------------------------------------------------
// Tiled SGEMM: C[M,N] = A[M,K] @ B[N,K]^T + bias[N], optional guard-clamp
// epilogue (for the QKV projection: clamps K (c==1) and V (c==2) channels
// against per-(b,h,ch) anchors).
// BM=BN=128, BK=8, 256 threads, 8x8 accum per thread.
// ---------------------------------------------------------------------------
template <bool CLAMP>
__global__ __launch_bounds__(256) void sgemm_bias_kernel(
    const float* __restrict__ A, const float* __restrict__ Bm,
    const float* __restrict__ bias, float* __restrict__ C,
    int M, int N, int K,
    const float* __restrict__ akmin, const float* __restrict__ akmax,
    const float* __restrict__ avmin, const float* __restrict__ avmax)
{
    __shared__ float As[8][128];
    __shared__ float Bs[8][128];

    const int tid = threadIdx.x;
    const int bm = blockIdx.y * 128;
    const int bn = blockIdx.x * 128;
    const int tx = tid & 15;        // 0..15 -> col group
    const int ty = tid >> 4;        // 0..15 -> row group

    const int lrow = tid >> 1;      // 0..127
    const int lk4  = (tid & 1) * 4; // 0 or 4

    const float* Aptr = A + (bm + lrow) * K + lk4;
    const float* Bptr = Bm + (bn + lrow) * K + lk4;

    float acc[8][8];
#pragma unroll
    for (int i = 0; i < 8; i++)
#pragma unroll
        for (int j = 0; j < 8; j++) acc[i][j] = 0.0f;

    for (int k0 = 0; k0 < K; k0 += 8) {
        float4 a4 = *(const float4*)(Aptr + k0);
        float4 b4 = *(const float4*)(Bptr + k0);
        if (k0) __syncthreads();
        As[lk4 + 0][lrow] = a4.x; As[lk4 + 1][lrow] = a4.y;
        As[lk4 + 2][lrow] = a4.z; As[lk4 + 3][lrow] = a4.w;
        Bs[lk4 + 0][lrow] = b4.x; Bs[lk4 + 1][lrow] = b4.y;
        Bs[lk4 + 2][lrow] = b4.z; Bs[lk4 + 3][lrow] = b4.w;
        __syncthreads();
#pragma unroll
        for (int kk = 0; kk < 8; kk++) {
            float ra[8], rb[8];
            *(float4*)(ra)     = *(const float4*)&As[kk][ty * 8];
            *(float4*)(ra + 4) = *(const float4*)&As[kk][ty * 8 + 4];
            *(float4*)(rb)     = *(const float4*)&Bs[kk][tx * 8];
            *(float4*)(rb + 4) = *(const float4*)&Bs[kk][tx * 8 + 4];
#pragma unroll
            for (int i = 0; i < 8; i++)
#pragma unroll
                for (int j = 0; j < 8; j++)
                    acc[i][j] = fmaf(ra[i], rb[j], acc[i][j]);
        }
    }

    // Epilogue
#pragma unroll
    for (int i = 0; i < 8; i++) {
        const int m = bm + ty * 8 + i;
#pragma unroll
        for (int j = 0; j < 8; j++) {
            const int n = bn + tx * 8 + j;
            float v = acc[i][j] + bias[n];
            if (CLAMP) {
                const int c = n >> 10;            // 0=q,1=k,2=v
                if (c >= 1) {
                    const int b  = m >> 11;       // m / S_ (S_=2048)
                    const int h  = (n & 1023) >> 6;
                    const int ch = n & 63;
                    const int ai = ((b << 4) + h) * 64 + ch;
                    const float amin = (c == 1) ? akmin[ai] : avmin[ai];
                    const float amax = (c == 1) ? akmax[ai] : avmax[ai];
                    float lo = fmaxf(v - EPS_, amin);
                    float hi = fminf(v + EPS_, amax);
                    lo = fminf(lo, hi);
                    v = fmaxf(lo, fminf(v, hi));
                }
            }
            C[m * N + n] = v;
        }
    }
}

// ---------------------------------------------------------------------------
// Flash-attention (fp32, online softmax).
// Block = (b, h, q-tile of 64 rows). 256 threads = 8 warps; warp owns 8 rows.
// Per lane: 2 kv-cols in S phase (j=lane, lane+32), 2 d-cols in PV phase.
// smem: sQ[64][64], sK[64][65] (padded: row index varies across lanes),
//       sV[64][64], sP[64][65]. Total 66048 B dynamic.
// ---------------------------------------------------------------------------
__global__ __launch_bounds__(256) void attn_kernel(
    const float* __restrict__ qkv, float* __restrict__ out)
{
    extern __shared__ float sm[];
    float* sQ = sm;               // 64*64
    float* sK = sQ + 64 * 64;     // 64*65
    float* sV = sK + 64 * 65;     // 64*64
    float* sP = sV + 64 * 64;     // 64*65

    const int qt = blockIdx.x;    // 0..31
    const int h  = blockIdx.y;    // 0..15
    const int b  = blockIdx.z;    // 0..1
    const int tid  = threadIdx.x;
    const int w    = tid >> 5;    // warp 0..7
    const int lane = tid & 31;

    const float scale = 0.125f;   // 1/sqrt(64)

    // Load Q tile (scaled). qkv[((b*S+s)*3 + c)*1024 + h*64 + ch]
#pragma unroll
    for (int it = 0; it < 4; it++) {
        const int idx = tid + it * 256;       // float4 idx 0..1023
        const int r  = idx >> 4;
        const int c4 = (idx & 15) << 2;
        const int s  = qt * 64 + r;
        const float4 v = *(const float4*)(qkv + ((b * S_ + s) * 3) * 1024 + h * 64 + c4);
        sQ[r * 64 + c4 + 0] = v.x * scale;
        sQ[r * 64 + c4 + 1] = v.y * scale;
        sQ[r * 64 + c4 + 2] = v.z * scale;
        sQ[r * 64 + c4 + 3] = v.w * scale;
    }

    float m_i[8], l_i[8], oacc[8][2];
#pragma unroll
    for (int i = 0; i < 8; i++) {
        m_i[i] = -1e30f; l_i[i] = 0.0f;
        oacc[i][0] = 0.0f; oacc[i][1] = 0.0f;
    }

    for (int kt = 0; kt < S_ / 64; kt++) {
        __syncthreads();
        // Load K (stride 65) and V (stride 64) tiles
#pragma unroll
        for (int it = 0; it < 4; it++) {
            const int idx = tid + it * 256;
            const int r  = idx >> 4;
            const int c4 = (idx & 15) << 2;
            const int s  = kt * 64 + r;
            const int base = ((b * S_ + s) * 3) * 1024 + h * 64 + c4;
            const float4 kv = *(const float4*)(qkv + base + 1024);
            sK[r * 65 + c4 + 0] = kv.x;
            sK[r * 65 + c4 + 1] = kv.y;
            sK[r * 65 + c4 + 2] = kv.z;
            sK[r * 65 + c4 + 3] = kv.w;
            const float4 vv = *(const float4*)(qkv + base + 2048);
            *(float4*)&sV[r * 64 + c4] = vv;
        }
        __syncthreads();

        // S = Qs @ K^T  (per warp: 8 rows x 64 cols; lane -> cols lane, lane+32)
        float sa[8][2];
#pragma unroll
        for (int i = 0; i < 8; i++) { sa[i][0] = 0.0f; sa[i][1] = 0.0f; }
#pragma unroll 16
        for (int d = 0; d < 64; d++) {
            const float k0 = sK[lane * 65 + d];
            const float k1 = sK[(lane + 32) * 65 + d];
#pragma unroll
            for (int i = 0; i < 8; i++) {
                const float q = sQ[(w * 8 + i) * 64 + d];
                sa[i][0] = fmaf(q, k0, sa[i][0]);
                sa[i][1] = fmaf(q, k1, sa[i][1]);
            }
        }

        // Online softmax per row; write P to smem (own rows only)
#pragma unroll
        for (int i = 0; i < 8; i++) {
            float mx = fmaxf(sa[i][0], sa[i][1]);
#pragma unroll
            for (int off = 16; off; off >>= 1)
                mx = fmaxf(mx, __shfl_xor_sync(0xffffffffu, mx, off));
            const float mnew = fmaxf(m_i[i], mx);
            const float p0 = __expf(sa[i][0] - mnew);
            const float p1 = __expf(sa[i][1] - mnew);
            float rs = p0 + p1;
#pragma unroll
            for (int off = 16; off; off >>= 1)
                rs += __shfl_xor_sync(0xffffffffu, rs, off);
            const float corr = __expf(m_i[i] - mnew);
            l_i[i] = l_i[i] * corr + rs;
            oacc[i][0] *= corr;
            oacc[i][1] *= corr;
            m_i[i] = mnew;
            sP[(w * 8 + i) * 65 + lane]      = p0;
            sP[(w * 8 + i) * 65 + lane + 32] = p1;
        }
        __syncwarp();

        // O += P @ V  (lane -> d-cols lane, lane+32)
#pragma unroll 16
        for (int j = 0; j < 64; j++) {
            const float v0 = sV[j * 64 + lane];
            const float v1 = sV[j * 64 + lane + 32];
#pragma unroll
            for (int i = 0; i < 8; i++) {
                const float p = sP[(w * 8 + i) * 65 + j];
                oacc[i][0] = fmaf(p, v0, oacc[i][0]);
                oacc[i][1] = fmaf(p, v1, oacc[i][1]);
            }
        }
    }

    // Epilogue: normalize, write [B,S,H,dk] layout
#pragma unroll
    for (int i = 0; i < 8; i++) {
        const float inv = 1.0f / l_i[i];
        const int s = qt * 64 + w * 8 + i;
        const int base = (b * S_ + s) * 1024 + h * 64;
        out[base + lane]      = oacc[i][0] * inv;
        out[base + lane + 32] = oacc[i][1] * inv;
    }
}

// ---------------------------------------------------------------------------
extern "C" void kernel_launch(void* const* d_in, const int* in_sizes, int n_in,
                              void* d_out, int out_size)
{
    const float* x      = (const float*)d_in[0];
    const float* qkv_w  = (const float*)d_in[1];
    const float* qkv_b  = (const float*)d_in[2];
    const float* out_w  = (const float*)d_in[3];
    const float* out_b  = (const float*)d_in[4];
    const float* akmin  = (const float*)d_in[5];
    const float* akmax  = (const float*)d_in[6];
    const float* avmin  = (const float*)d_in[7];
    const float* avmax  = (const float*)d_in[8];
    float* out = (float*)d_out;

    float* qkv_buf = nullptr;
    float* attn_buf = nullptr;
    cudaGetSymbolAddress((void**)&qkv_buf, g_qkv);
    cudaGetSymbolAddress((void**)&attn_buf, g_attn);

    const int attn_smem = (64 * 64 + 64 * 65 + 64 * 64 + 64 * 65) * (int)sizeof(float);
    cudaFuncSetAttribute(attn_kernel, cudaFuncAttributeMaxDynamicSharedMemorySize, attn_smem);

    // 1) QKV projection + bias + guard-clamp of K,V
    {
        dim3 grid(N_QKV / 128, M_ROWS / 128);
        sgemm_bias_kernel<true><<<grid, 256>>>(
            x, qkv_w, qkv_b, qkv_buf, M_ROWS, N_QKV, D_,
            akmin, akmax, avmin, avmax);
    }

    // 2) Attention (flash-style, fused softmax), writes [B,S,D]
    {
        dim3 grid(S_ / 64, H_, B_);
        attn_kernel<<<grid, 256, attn_smem>>>(qkv_buf, attn_buf);
    }

    // 3) Output projection + bias
    {
        dim3 grid(D_ / 128, M_ROWS / 128);
        sgemm_bias_kernel<false><<<grid, 256>>>(
            attn_buf, out_w, out_b, out, M_ROWS, D_, D_,
            nullptr, nullptr, nullptr, nullptr);
    }
}

// round 3
// speedup vs baseline: 1.3284x; 1.3284x over previous
#include <cuda_runtime.h>
#include <cuda_bf16.h>
#include <cstdint>

#define B_   2
#define S_   2048
#define D_   1024
#define H_   16
#define DK_  64
#define EPS_ 0.1f
#define M_ROWS (B_ * S_)          // 4096
#define N_QKV  (3 * D_)           // 3072

// Scratch (allocation-free requirement -> __device__ globals)
__device__ float g_qkv[M_ROWS * N_QKV];     // [B,S,3,H,dk]
__device__ float g_attn[M_ROWS * D_];       // [B,S,D]
__device__ __nv_bfloat16 g_ah[M_ROWS * D_]; // split-hi of A operand (x, then attn out)
__device__ __nv_bfloat16 g_al[M_ROWS * D_]; // split-lo
__device__ __nv_bfloat16 g_wqh[N_QKV * D_];
__device__ __nv_bfloat16 g_wql[N_QKV * D_];
__device__ __nv_bfloat16 g_woh[D_ * D_];
__device__ __nv_bfloat16 g_wol[D_ * D_];

// ---------------------------------------------------------------------------
// helpers
// ---------------------------------------------------------------------------
__device__ __forceinline__ uint32_t smem_u32(const void* p) {
    return (uint32_t)__cvta_generic_to_shared(p);
}
__device__ __forceinline__ void ldsm_x4(uint32_t& r0, uint32_t& r1, uint32_t& r2,
                                        uint32_t& r3, uint32_t addr) {
    asm volatile("ldmatrix.sync.aligned.m8n8.x4.shared.b16 {%0,%1,%2,%3}, [%4];"
                 : "=r"(r0), "=r"(r1), "=r"(r2), "=r"(r3) : "r"(addr));
}
__device__ __forceinline__ void ldsm_x2(uint32_t& r0, uint32_t& r1, uint32_t addr) {
    asm volatile("ldmatrix.sync.aligned.m8n8.x2.shared.b16 {%0,%1}, [%2];"
                 : "=r"(r0), "=r"(r1) : "r"(addr));
}
__device__ __forceinline__ void mma16816(float c[4], const uint32_t a[4],
                                         const uint32_t b[2]) {
    asm volatile(
        "mma.sync.aligned.m16n8k16.row.col.f32.bf16.bf16.f32 "
        "{%0,%1,%2,%3}, {%4,%5,%6,%7}, {%8,%9}, {%0,%1,%2,%3};"
        : "+f"(c[0]), "+f"(c[1]), "+f"(c[2]), "+f"(c[3])
        : "r"(a[0]), "r"(a[1]), "r"(a[2]), "r"(a[3]), "r"(b[0]), "r"(b[1]));
}
__device__ __forceinline__ void ffma2(unsigned long long& d, unsigned long long a,
                                      unsigned long long b) {
    asm volatile("fma.rn.f32x2 %0, %1, %2, %0;" : "+l"(d) : "l"(a), "l"(b));
}
__device__ __forceinline__ float2 unpack2(unsigned long long v) {
    float2 r;
    asm("mov.b64 {%0,%1}, %2;" : "=f"(r.x), "=f"(r.y) : "l"(v));
    return r;
}

// ---------------------------------------------------------------------------
// fp32 -> (hi,lo) bf16 split
// ---------------------------------------------------------------------------
__global__ void split_kernel(const float* __restrict__ in,
                             __nv_bfloat16* __restrict__ hi,
                             __nv_bfloat16* __restrict__ lo, int n4) {
    int i = blockIdx.x * blockDim.x + threadIdx.x;
    if (i >= n4) return;
    float4 f = ((const float4*)in)[i];
    __nv_bfloat16 h0 = __float2bfloat16(f.x);
    __nv_bfloat16 h1 = __float2bfloat16(f.y);
    __nv_bfloat16 h2 = __float2bfloat16(f.z);
    __nv_bfloat16 h3 = __float2bfloat16(f.w);
    __nv_bfloat16 l0 = __float2bfloat16(f.x - __bfloat162float(h0));
    __nv_bfloat16 l1 = __float2bfloat16(f.y - __bfloat162float(h1));
    __nv_bfloat16 l2 = __float2bfloat16(f.z - __bfloat162float(h2));
    __nv_bfloat16 l3 = __float2bfloat16(f.w - __bfloat162float(h3));
    __nv_bfloat162* hp = (__nv_bfloat162*)hi;
    __nv_bfloat162* lp = (__nv_bfloat162*)lo;
    hp[2 * i]     = __halves2bfloat162(h0, h1);
    hp[2 * i + 1] = __halves2bfloat162(h2, h3);
    lp[2 * i]     = __halves2bfloat162(l0, l1);
    lp[2 * i + 1] = __halves2bfloat162(l2, l3);
}

// ---------------------------------------------------------------------------
// guard clamp (QKV epilogue)
// ---------------------------------------------------------------------------
__device__ __forceinline__ float guard_clamp(
    float v, int m, int n,
    const float* __restrict__ akmin, const float* __restrict__ akmax,
    const float* __restrict__ avmin, const float* __restrict__ avmax) {
    const int c = n >> 10;                 // 0=q,1=k,2=v
    if (c >= 1) {
        const int b  = m >> 11;            // m / 2048
        const int h  = (n & 1023) >> 6;
        const int ch = n & 63;
        const int ai = ((b << 4) + h) * 64 + ch;
        const float amin = (c == 1) ? akmin[ai] : avmin[ai];
        const float amax = (c == 1) ? akmax[ai] : avmax[ai];
        float lo = fmaxf(v - EPS_, amin);
        float hi = fminf(v + EPS_, amax);
        lo = fminf(lo, hi);
        v = fmaxf(lo, fminf(v, hi));
    }
    return v;
}

// ---------------------------------------------------------------------------
// Split-bf16 tensor-core GEMM:  C[M,N] = A[M,K] @ B[N,K]^T + bias
// D = Ah*Bh + Ah*Bl + Al*Bh  (fp32 accumulate).
// Block 128x128, BK=16, 256 thr = 8 warps (2 M x 4 N), warp tile 64x32.
// smem rows padded to 24 bf16 (48B) -> conflict-free ldmatrix.
// ---------------------------------------------------------------------------
template <bool CLAMP>
__global__ __launch_bounds__(256) void gemm_bf16s_kernel(
    const __nv_bfloat16* __restrict__ Ah, const __nv_bfloat16* __restrict__ Al,
    const __nv_bfloat16* __restrict__ Bh, const __nv_bfloat16* __restrict__ Bl,
    const float* __restrict__ bias, float* __restrict__ C,
    int M, int N, int K,
    const float* __restrict__ akmin, const float* __restrict__ akmax,
    const float* __restrict__ avmin, const float* __restrict__ avmax)
{
    __shared__ __nv_bfloat16 sAh[128][24];
    __shared__ __nv_bfloat16 sAl[128][24];
    __shared__ __nv_bfloat16 sBh[128][24];
    __shared__ __nv_bfloat16 sBl[128][24];

    const int tid  = threadIdx.x;
    const int wid  = tid >> 5;
    const int lane = tid & 31;
    const int warp_m = (wid & 1) * 64;
    const int warp_n = (wid >> 1) * 32;
    const int bm = blockIdx.y * 128;
    const int bn = blockIdx.x * 128;

    // loader mapping: 2 threads per row, each brings 8 bf16 (16B = one 32B sector pair)
    const int row = tid >> 1;
    const int ko  = (tid & 1) * 8;
    const __nv_bfloat16* pAh = Ah + (size_t)(bm + row) * K + ko;
    const __nv_bfloat16* pAl = Al + (size_t)(bm + row) * K + ko;
    const __nv_bfloat16* pBh = Bh + (size_t)(bn + row) * K + ko;
    const __nv_bfloat16* pBl = Bl + (size_t)(bn + row) * K + ko;

    float c[4][4][4];
#pragma unroll
    for (int mt = 0; mt < 4; mt++)
#pragma unroll
        for (int nt = 0; nt < 4; nt++)
#pragma unroll
            for (int e = 0; e < 4; e++) c[mt][nt][e] = 0.0f;

    const int KS = K >> 4;
    uint4 ra_h = *(const uint4*)pAh;
    uint4 ra_l = *(const uint4*)pAl;
    uint4 rb_h = *(const uint4*)pBh;
    uint4 rb_l = *(const uint4*)pBl;

    const int ar = lane & 15, ac = (lane >> 4) << 3;
    const int br = lane & 7,  bc = ((lane >> 3) & 1) << 3;

    for (int ks = 0; ks < KS; ks++) {
        *(uint4*)&sAh[row][ko] = ra_h;
        *(uint4*)&sAl[row][ko] = ra_l;
        *(uint4*)&sBh[row][ko] = rb_h;
        *(uint4*)&sBl[row][ko] = rb_l;
        __syncthreads();
        if (ks + 1 < KS) {
            const int off = (ks + 1) * 16;
            ra_h = *(const uint4*)(pAh + off);
            ra_l = *(const uint4*)(pAl + off);
            rb_h = *(const uint4*)(pBh + off);
            rb_l = *(const uint4*)(pBl + off);
        }

        uint32_t afh[4][4], afl[4][4], bfh[4][2], bfl[4][2];
#pragma unroll
        for (int mt = 0; mt < 4; mt++) {
            const int r = warp_m + mt * 16 + ar;
            ldsm_x4(afh[mt][0], afh[mt][1], afh[mt][2], afh[mt][3],
                    smem_u32(&sAh[r][ac]));
            ldsm_x4(afl[mt][0], afl[mt][1], afl[mt][2], afl[mt][3],
                    smem_u32(&sAl[r][ac]));
        }
#pragma unroll
        for (int nt = 0; nt < 4; nt++) {
            const int r = warp_n + nt * 8 + br;
            ldsm_x2(bfh[nt][0], bfh[nt][1], smem_u32(&sBh[r][bc]));
            ldsm_x2(bfl[nt][0], bfl[nt][1], smem_u32(&sBl[r][bc]));
        }
#pragma unroll
        for (int mt = 0; mt < 4; mt++)
#pragma unroll
            for (int nt = 0; nt < 4; nt++) {
                mma16816(c[mt][nt], afh[mt], bfh[nt]);
                mma16816(c[mt][nt], afh[mt], bfl[nt]);
                mma16816(c[mt][nt], afl[mt], bfh[nt]);
            }
        __syncthreads();
    }

    // Epilogue: bias + optional clamp; fragment c0..c3 = C[g][2t],C[g][2t+1],C[g+8][..]
    const int g = lane >> 2, t = lane & 3;
#pragma unroll
    for (int mt = 0; mt < 4; mt++) {
#pragma unroll
        for (int nt = 0; nt < 4; nt++) {
            const int n0 = bn + warp_n + nt * 8 + t * 2;
            const float b0 = bias[n0], b1 = bias[n0 + 1];
#pragma unroll
            for (int half = 0; half < 2; half++) {
                const int m = bm + warp_m + mt * 16 + g + half * 8;
                float v0 = c[mt][nt][half * 2 + 0] + b0;
                float v1 = c[mt][nt][half * 2 + 1] + b1;
                if (CLAMP) {
                    v0 = guard_clamp(v0, m, n0,     akmin, akmax, avmin, avmax);
                    v1 = guard_clamp(v1, m, n0 + 1, akmin, akmax, avmin, avmax);
                }
                *(float2*)&C[(size_t)m * N + n0] = make_float2(v0, v1);
            }
        }
    }
}

// ---------------------------------------------------------------------------
// Flash-attention (fp32 math, packed f32x2 in S-phase, float4 P loads in PV).
// Block = (b, h, 64-query tile). 256 threads = 8 warps; warp owns 8 rows.
// sK/sP stride 68 (16B-aligned, conflict-free v2.u64 / float4), sQ/sV stride 64.
// ---------------------------------------------------------------------------
__global__ __launch_bounds__(256) void attn_kernel(
    const float* __restrict__ qkv, float* __restrict__ out)
{
    extern __shared__ float sm[];
    float* sQ = sm;               // 64*64
    float* sK = sQ + 64 * 64;     // 64*68
    float* sV = sK + 64 * 68;     // 64*64
    float* sP = sV + 64 * 64;     // 64*68

    const int qt = blockIdx.x;
    const int h  = blockIdx.y;
    const int b  = blockIdx.z;
    const int tid  = threadIdx.x;
    const int w    = tid >> 5;
    const int lane = tid & 31;
    const float scale = 0.125f;   // 1/sqrt(64)

#pragma unroll
    for (int it = 0; it < 4; it++) {
        const int idx = tid + it * 256;
        const int r  = idx >> 4;
        const int c4 = (idx & 15) << 2;
        const int s  = qt * 64 + r;
        float4 v = *(const float4*)(qkv + ((b * S_ + s) * 3) * 1024 + h * 64 + c4);
        v.x *= scale; v.y *= scale; v.z *= scale; v.w *= scale;
        *(float4*)&sQ[r * 64 + c4] = v;
    }

    float m_i[8], l_i[8], oacc[8][2];
#pragma unroll
    for (int i = 0; i < 8; i++) {
        m_i[i] = -1e30f; l_i[i] = 0.0f;
        oacc[i][0] = 0.0f; oacc[i][1] = 0.0f;
    }

    for (int kt = 0; kt < S_ / 64; kt++) {
        __syncthreads();
#pragma unroll
        for (int it = 0; it < 4; it++) {
            const int idx = tid + it * 256;
            const int r  = idx >> 4;
            const int c4 = (idx & 15) << 2;
            const int s  = kt * 64 + r;
            const int base = ((b * S_ + s) * 3) * 1024 + h * 64 + c4;
            *(float4*)&sK[r * 68 + c4] = *(const float4*)(qkv + base + 1024);
            *(float4*)&sV[r * 64 + c4] = *(const float4*)(qkv + base + 2048);
        }
        __syncthreads();

        // S = Qs @ K^T, packed over d-pairs (fma.rn.f32x2)
        unsigned long long sa2[8][2];
#pragma unroll
        for (int i = 0; i < 8; i++) { sa2[i][0] = 0ull; sa2[i][1] = 0ull; }
#pragma unroll 4
        for (int d0 = 0; d0 < 64; d0 += 4) {
            const ulonglong2 k0 = *(const ulonglong2*)&sK[lane * 68 + d0];
            const ulonglong2 k1 = *(const ulonglong2*)&sK[(lane + 32) * 68 + d0];
#pragma unroll
            for (int i = 0; i < 8; i++) {
                const ulonglong2 q = *(const ulonglong2*)&sQ[(w * 8 + i) * 64 + d0];
                ffma2(sa2[i][0], q.x, k0.x);
                ffma2(sa2[i][1], q.x, k1.x);
                ffma2(sa2[i][0], q.y, k0.y);
                ffma2(sa2[i][1], q.y, k1.y);
            }
        }

        // Online softmax per row
#pragma unroll
        for (int i = 0; i < 8; i++) {
            const float2 t0 = unpack2(sa2[i][0]);
            const float2 t1 = unpack2(sa2[i][1]);
            const float s0 = t0.x + t0.y;
            const float s1 = t1.x + t1.y;
            float mx = fmaxf(s0, s1);
#pragma unroll
            for (int off = 16; off; off >>= 1)
                mx = fmaxf(mx, __shfl_xor_sync(0xffffffffu, mx, off));
            const float mnew = fmaxf(m_i[i], mx);
            const float p0 = __expf(s0 - mnew);
            const float p1 = __expf(s1 - mnew);
            float rs = p0 + p1;
#pragma unroll
            for (int off = 16; off; off >>= 1)
                rs += __shfl_xor_sync(0xffffffffu, rs, off);
            const float corr = __expf(m_i[i] - mnew);
            l_i[i] = l_i[i] * corr + rs;
            oacc[i][0] *= corr;
            oacc[i][1] *= corr;
            m_i[i] = mnew;
            sP[(w * 8 + i) * 68 + lane]      = p0;
            sP[(w * 8 + i) * 68 + lane + 32] = p1;
        }
        __syncwarp();

        // O += P @ V  (float4 P loads, scalar V)
#pragma unroll 4
        for (int j0 = 0; j0 < 64; j0 += 4) {
            float v0[4], v1[4];
#pragma unroll
            for (int u = 0; u < 4; u++) {
                v0[u] = sV[(j0 + u) * 64 + lane];
                v1[u] = sV[(j0 + u) * 64 + lane + 32];
            }
#pragma unroll
            for (int i = 0; i < 8; i++) {
                const float4 p = *(const float4*)&sP[(w * 8 + i) * 68 + j0];
                oacc[i][0] += p.x * v0[0] + p.y * v0[1] + p.z * v0[2] + p.w * v0[3];
                oacc[i][1] += p.x * v1[0] + p.y * v1[1] + p.z * v1[2] + p.w * v1[3];
            }
        }
    }

    // Epilogue: normalize, write [B,S,H,dk] = [B,S,D]
#pragma unroll
    for (int i = 0; i < 8; i++) {
        const float inv = 1.0f / l_i[i];
        const int s = qt * 64 + w * 8 + i;
        const int base = (b * S_ + s) * 1024 + h * 64;
        out[base + lane]      = oacc[i][0] * inv;
        out[base + lane + 32] = oacc[i][1] * inv;
    }
}

// ---------------------------------------------------------------------------
extern "C" void kernel_launch(void* const* d_in, const int* in_sizes, int n_in,
                              void* d_out, int out_size)
{
    const float* x      = (const float*)d_in[0];
    const float* qkv_w  = (const float*)d_in[1];
    const float* qkv_b  = (const float*)d_in[2];
    const float* out_w  = (const float*)d_in[3];
    const float* out_b  = (const float*)d_in[4];
    const float* akmin  = (const float*)d_in[5];
    const float* akmax  = (const float*)d_in[6];
    const float* avmin  = (const float*)d_in[7];
    const float* avmax  = (const float*)d_in[8];
    float* out = (float*)d_out;

    float *qkv_buf = nullptr, *attn_buf = nullptr;
    __nv_bfloat16 *ah, *al, *wqh, *wql, *woh, *wol;
    cudaGetSymbolAddress((void**)&qkv_buf, g_qkv);
    cudaGetSymbolAddress((void**)&attn_buf, g_attn);
    cudaGetSymbolAddress((void**)&ah,  g_ah);
    cudaGetSymbolAddress((void**)&al,  g_al);
    cudaGetSymbolAddress((void**)&wqh, g_wqh);
    cudaGetSymbolAddress((void**)&wql, g_wql);
    cudaGetSymbolAddress((void**)&woh, g_woh);
    cudaGetSymbolAddress((void**)&wol, g_wol);

    const int attn_smem = (64 * 64 + 64 * 68 + 64 * 64 + 64 * 68) * (int)sizeof(float);
    cudaFuncSetAttribute(attn_kernel, cudaFuncAttributeMaxDynamicSharedMemorySize, attn_smem);

    // 0) split fp32 -> hi/lo bf16
    split_kernel<<<(M_ROWS * D_ / 4 + 255) / 256, 256>>>(x, ah, al, M_ROWS * D_ / 4);
    split_kernel<<<(N_QKV * D_ / 4 + 255) / 256, 256>>>(qkv_w, wqh, wql, N_QKV * D_ / 4);
    split_kernel<<<(D_ * D_ / 4 + 255) / 256, 256>>>(out_w, woh, wol, D_ * D_ / 4);

    // 1) QKV projection + bias + guard-clamp (tensor cores)
    {
        dim3 grid(N_QKV / 128, M_ROWS / 128);
        gemm_bf16s_kernel<true><<<grid, 256>>>(
            ah, al, wqh, wql, qkv_b, qkv_buf, M_ROWS, N_QKV, D_,
            akmin, akmax, avmin, avmax);
    }

    // 2) Attention
    {
        dim3 grid(S_ / 64, H_, B_);
        attn_kernel<<<grid, 256, attn_smem>>>(qkv_buf, attn_buf);
    }

    // 3) split attention output, then output projection
    split_kernel<<<(M_ROWS * D_ / 4 + 255) / 256, 256>>>(attn_buf, ah, al, M_ROWS * D_ / 4);
    {
        dim3 grid(D_ / 128, M_ROWS / 128);
        gemm_bf16s_kernel<false><<<grid, 256>>>(
            ah, al, woh, wol, out_b, out, M_ROWS, D_, D_,
            nullptr, nullptr, nullptr, nullptr);
    }
}

// round 4
// speedup vs baseline: 2.4284x; 1.8281x over previous
#include <cuda_runtime.h>
#include <cuda_bf16.h>
#include <cstdint>

#define B_   2
#define S_   2048
#define D_   1024
#define H_   16
#define DK_  64
#define EPS_ 0.1f
#define M_ROWS (B_ * S_)          // 4096
#define N_QKV  (3 * D_)           // 3072

// Scratch (allocation-free requirement -> __device__ globals)
__device__ float g_qkv[M_ROWS * N_QKV];     // [B,S,3,H,dk]
__device__ float g_attn[M_ROWS * D_];       // [B,S,D]
__device__ __nv_bfloat16 g_ah[M_ROWS * D_];
__device__ __nv_bfloat16 g_al[M_ROWS * D_];
__device__ __nv_bfloat16 g_wqh[N_QKV * D_];
__device__ __nv_bfloat16 g_wql[N_QKV * D_];
__device__ __nv_bfloat16 g_woh[D_ * D_];
__device__ __nv_bfloat16 g_wol[D_ * D_];

// ---------------------------------------------------------------------------
// helpers
// ---------------------------------------------------------------------------
__device__ __forceinline__ uint32_t smem_u32(const void* p) {
    return (uint32_t)__cvta_generic_to_shared(p);
}
__device__ __forceinline__ void ldsm_x4(uint32_t& r0, uint32_t& r1, uint32_t& r2,
                                        uint32_t& r3, uint32_t addr) {
    asm volatile("ldmatrix.sync.aligned.m8n8.x4.shared.b16 {%0,%1,%2,%3}, [%4];"
                 : "=r"(r0), "=r"(r1), "=r"(r2), "=r"(r3) : "r"(addr));
}
__device__ __forceinline__ void ldsm_x2(uint32_t& r0, uint32_t& r1, uint32_t addr) {
    asm volatile("ldmatrix.sync.aligned.m8n8.x2.shared.b16 {%0,%1}, [%2];"
                 : "=r"(r0), "=r"(r1) : "r"(addr));
}
__device__ __forceinline__ void ldsm_x2_t(uint32_t& r0, uint32_t& r1, uint32_t addr) {
    asm volatile("ldmatrix.sync.aligned.m8n8.x2.trans.shared.b16 {%0,%1}, [%2];"
                 : "=r"(r0), "=r"(r1) : "r"(addr));
}
__device__ __forceinline__ void mma16816(float c[4], const uint32_t a[4],
                                         const uint32_t b[2]) {
    asm volatile(
        "mma.sync.aligned.m16n8k16.row.col.f32.bf16.bf16.f32 "
        "{%0,%1,%2,%3}, {%4,%5,%6,%7}, {%8,%9}, {%0,%1,%2,%3};"
        : "+f"(c[0]), "+f"(c[1]), "+f"(c[2]), "+f"(c[3])
        : "r"(a[0]), "r"(a[1]), "r"(a[2]), "r"(a[3]), "r"(b[0]), "r"(b[1]));
}
__device__ __forceinline__ uint32_t pack_hi2(float x, float y) {
    __nv_bfloat162 t = __floats2bfloat162_rn(x, y);
    return *(uint32_t*)&t;
}
__device__ __forceinline__ uint32_t pack_lo2(float x, float y) {
    float hx = __bfloat162float(__float2bfloat16(x));
    float hy = __bfloat162float(__float2bfloat16(y));
    __nv_bfloat162 t = __floats2bfloat162_rn(x - hx, y - hy);
    return *(uint32_t*)&t;
}

// ---------------------------------------------------------------------------
// fp32 -> (hi,lo) bf16 split
// ---------------------------------------------------------------------------
__global__ void split_kernel(const float* __restrict__ in,
                             __nv_bfloat16* __restrict__ hi,
                             __nv_bfloat16* __restrict__ lo, int n4) {
    int i = blockIdx.x * blockDim.x + threadIdx.x;
    if (i >= n4) return;
    float4 f = ((const float4*)in)[i];
    __nv_bfloat16 h0 = __float2bfloat16(f.x);
    __nv_bfloat16 h1 = __float2bfloat16(f.y);
    __nv_bfloat16 h2 = __float2bfloat16(f.z);
    __nv_bfloat16 h3 = __float2bfloat16(f.w);
    __nv_bfloat16 l0 = __float2bfloat16(f.x - __bfloat162float(h0));
    __nv_bfloat16 l1 = __float2bfloat16(f.y - __bfloat162float(h1));
    __nv_bfloat16 l2 = __float2bfloat16(f.z - __bfloat162float(h2));
    __nv_bfloat16 l3 = __float2bfloat16(f.w - __bfloat162float(h3));
    __nv_bfloat162* hp = (__nv_bfloat162*)hi;
    __nv_bfloat162* lp = (__nv_bfloat162*)lo;
    hp[2 * i]     = __halves2bfloat162(h0, h1);
    hp[2 * i + 1] = __halves2bfloat162(h2, h3);
    lp[2 * i]     = __halves2bfloat162(l0, l1);
    lp[2 * i + 1] = __halves2bfloat162(l2, l3);
}

// ---------------------------------------------------------------------------
// guard clamp (QKV epilogue)
// ---------------------------------------------------------------------------
__device__ __forceinline__ float guard_clamp(
    float v, int m, int n,
    const float* __restrict__ akmin, const float* __restrict__ akmax,
    const float* __restrict__ avmin, const float* __restrict__ avmax) {
    const int c = n >> 10;                 // 0=q,1=k,2=v
    if (c >= 1) {
        const int b  = m >> 11;
        const int h  = (n & 1023) >> 6;
        const int ch = n & 63;
        const int ai = ((b << 4) + h) * 64 + ch;
        const float amin = (c == 1) ? akmin[ai] : avmin[ai];
        const float amax = (c == 1) ? akmax[ai] : avmax[ai];
        float lo = fmaxf(v - EPS_, amin);
        float hi = fminf(v + EPS_, amax);
        lo = fminf(lo, hi);
        v = fmaxf(lo, fminf(v, hi));
    }
    return v;
}

// ---------------------------------------------------------------------------
// Split-bf16 tensor-core GEMM (unchanged from round 3)
// ---------------------------------------------------------------------------
template <bool CLAMP>
__global__ __launch_bounds__(256) void gemm_bf16s_kernel(
    const __nv_bfloat16* __restrict__ Ah, const __nv_bfloat16* __restrict__ Al,
    const __nv_bfloat16* __restrict__ Bh, const __nv_bfloat16* __restrict__ Bl,
    const float* __restrict__ bias, float* __restrict__ C,
    int M, int N, int K,
    const float* __restrict__ akmin, const float* __restrict__ akmax,
    const float* __restrict__ avmin, const float* __restrict__ avmax)
{
    __shared__ __nv_bfloat16 sAh[128][24];
    __shared__ __nv_bfloat16 sAl[128][24];
    __shared__ __nv_bfloat16 sBh[128][24];
    __shared__ __nv_bfloat16 sBl[128][24];

    const int tid  = threadIdx.x;
    const int wid  = tid >> 5;
    const int lane = tid & 31;
    const int warp_m = (wid & 1) * 64;
    const int warp_n = (wid >> 1) * 32;
    const int bm = blockIdx.y * 128;
    const int bn = blockIdx.x * 128;

    const int row = tid >> 1;
    const int ko  = (tid & 1) * 8;
    const __nv_bfloat16* pAh = Ah + (size_t)(bm + row) * K + ko;
    const __nv_bfloat16* pAl = Al + (size_t)(bm + row) * K + ko;
    const __nv_bfloat16* pBh = Bh + (size_t)(bn + row) * K + ko;
    const __nv_bfloat16* pBl = Bl + (size_t)(bn + row) * K + ko;

    float c[4][4][4];
#pragma unroll
    for (int mt = 0; mt < 4; mt++)
#pragma unroll
        for (int nt = 0; nt < 4; nt++)
#pragma unroll
            for (int e = 0; e < 4; e++) c[mt][nt][e] = 0.0f;

    const int KS = K >> 4;
    uint4 ra_h = *(const uint4*)pAh;
    uint4 ra_l = *(const uint4*)pAl;
    uint4 rb_h = *(const uint4*)pBh;
    uint4 rb_l = *(const uint4*)pBl;

    const int ar = lane & 15, ac = (lane >> 4) << 3;
    const int br = lane & 7,  bc = ((lane >> 3) & 1) << 3;

    for (int ks = 0; ks < KS; ks++) {
        *(uint4*)&sAh[row][ko] = ra_h;
        *(uint4*)&sAl[row][ko] = ra_l;
        *(uint4*)&sBh[row][ko] = rb_h;
        *(uint4*)&sBl[row][ko] = rb_l;
        __syncthreads();
        if (ks + 1 < KS) {
            const int off = (ks + 1) * 16;
            ra_h = *(const uint4*)(pAh + off);
            ra_l = *(const uint4*)(pAl + off);
            rb_h = *(const uint4*)(pBh + off);
            rb_l = *(const uint4*)(pBl + off);
        }

        uint32_t afh[4][4], afl[4][4], bfh[4][2], bfl[4][2];
#pragma unroll
        for (int mt = 0; mt < 4; mt++) {
            const int r = warp_m + mt * 16 + ar;
            ldsm_x4(afh[mt][0], afh[mt][1], afh[mt][2], afh[mt][3],
                    smem_u32(&sAh[r][ac]));
            ldsm_x4(afl[mt][0], afl[mt][1], afl[mt][2], afl[mt][3],
                    smem_u32(&sAl[r][ac]));
        }
#pragma unroll
        for (int nt = 0; nt < 4; nt++) {
            const int r = warp_n + nt * 8 + br;
            ldsm_x2(bfh[nt][0], bfh[nt][1], smem_u32(&sBh[r][bc]));
            ldsm_x2(bfl[nt][0], bfl[nt][1], smem_u32(&sBl[r][bc]));
        }
#pragma unroll
        for (int mt = 0; mt < 4; mt++)
#pragma unroll
            for (int nt = 0; nt < 4; nt++) {
                mma16816(c[mt][nt], afh[mt], bfh[nt]);
                mma16816(c[mt][nt], afh[mt], bfl[nt]);
                mma16816(c[mt][nt], afl[mt], bfh[nt]);
            }
        __syncthreads();
    }

    const int g = lane >> 2, t = lane & 3;
#pragma unroll
    for (int mt = 0; mt < 4; mt++) {
#pragma unroll
        for (int nt = 0; nt < 4; nt++) {
            const int n0 = bn + warp_n + nt * 8 + t * 2;
            const float b0 = bias[n0], b1 = bias[n0 + 1];
#pragma unroll
            for (int half = 0; half < 2; half++) {
                const int m = bm + warp_m + mt * 16 + g + half * 8;
                float v0 = c[mt][nt][half * 2 + 0] + b0;
                float v1 = c[mt][nt][half * 2 + 1] + b1;
                if (CLAMP) {
                    v0 = guard_clamp(v0, m, n0,     akmin, akmax, avmin, avmax);
                    v1 = guard_clamp(v1, m, n0 + 1, akmin, akmax, avmin, avmax);
                }
                *(float2*)&C[(size_t)m * N + n0] = make_float2(v0, v1);
            }
        }
    }
}

// ---------------------------------------------------------------------------
// Tensor-core flash attention, split-bf16 3-term for QK^T and PV.
// Block = (b,h, 64-row Q tile), 128 threads = 4 warps, warp owns 16 q-rows.
// smem (dynamic): Qh,Ql,Kh,Kl,Vh,Vl each [64][72] bf16 = 55296 B.
// ---------------------------------------------------------------------------
#define STR_ 72

__global__ __launch_bounds__(128) void attn_tc_kernel(
    const float* __restrict__ qkv, float* __restrict__ out)
{
    extern __shared__ __nv_bfloat16 sb[];
    __nv_bfloat16* sQh = sb;
    __nv_bfloat16* sQl = sQh + 64 * STR_;
    __nv_bfloat16* sKh = sQl + 64 * STR_;
    __nv_bfloat16* sKl = sKh + 64 * STR_;
    __nv_bfloat16* sVh = sKl + 64 * STR_;
    __nv_bfloat16* sVl = sVh + 64 * STR_;

    const int qt = blockIdx.x, h = blockIdx.y, b = blockIdx.z;
    const int tid = threadIdx.x, w = tid >> 5, lane = tid & 31;
    const int g = lane >> 2, t = lane & 3;

    // ---- load Q tile: scale by 1/8 (exact), split to bf16 hi/lo ----
#pragma unroll
    for (int it = 0; it < 8; it++) {
        const int idx = tid + it * 128;          // float4 index 0..1023
        const int r = idx >> 4, c4 = (idx & 15) << 2;
        const float4 v = *(const float4*)(
            qkv + ((size_t)(b * S_ + qt * 64 + r) * 3) * 1024 + h * 64 + c4);
        float f0 = v.x * 0.125f, f1 = v.y * 0.125f;
        float f2 = v.z * 0.125f, f3 = v.w * 0.125f;
        uint2 hh, ll;
        hh.x = pack_hi2(f0, f1); hh.y = pack_hi2(f2, f3);
        ll.x = pack_lo2(f0, f1); ll.y = pack_lo2(f2, f3);
        *(uint2*)&sQh[r * STR_ + c4] = hh;
        *(uint2*)&sQl[r * STR_ + c4] = ll;
    }
    __syncthreads();

    // ---- hoist Q fragments (4 k-steps) ----
    uint32_t aqh[4][4], aql[4][4];
    const int ar = lane & 15, ac8 = (lane >> 4) << 3;
#pragma unroll
    for (int k = 0; k < 4; k++) {
        const int roff = (w * 16 + ar) * STR_ + ac8 + k * 16;
        ldsm_x4(aqh[k][0], aqh[k][1], aqh[k][2], aqh[k][3], smem_u32(&sQh[roff]));
        ldsm_x4(aql[k][0], aql[k][1], aql[k][2], aql[k][3], smem_u32(&sQl[roff]));
    }

    float o[8][4];
#pragma unroll
    for (int dt = 0; dt < 8; dt++)
#pragma unroll
        for (int e = 0; e < 4; e++) o[dt][e] = 0.0f;
    float m0 = -1e30f, m1 = -1e30f, l0 = 0.0f, l1 = 0.0f;

    const int kr = lane & 7, kc = ((lane >> 3) & 1) << 3;
    const int vr = lane & 15;

    for (int kt = 0; kt < S_ / 64; kt++) {
        __syncthreads();
        // ---- load K,V tile, split on the fly ----
#pragma unroll
        for (int it = 0; it < 8; it++) {
            const int idx = tid + it * 128;
            const int r = idx >> 4, c4 = (idx & 15) << 2;
            const size_t base =
                ((size_t)(b * S_ + kt * 64 + r) * 3) * 1024 + h * 64 + c4;
            const float4 kv = *(const float4*)(qkv + base + 1024);
            uint2 hh, ll;
            hh.x = pack_hi2(kv.x, kv.y); hh.y = pack_hi2(kv.z, kv.w);
            ll.x = pack_lo2(kv.x, kv.y); ll.y = pack_lo2(kv.z, kv.w);
            *(uint2*)&sKh[r * STR_ + c4] = hh;
            *(uint2*)&sKl[r * STR_ + c4] = ll;
            const float4 vv = *(const float4*)(qkv + base + 2048);
            hh.x = pack_hi2(vv.x, vv.y); hh.y = pack_hi2(vv.z, vv.w);
            ll.x = pack_lo2(vv.x, vv.y); ll.y = pack_lo2(vv.z, vv.w);
            *(uint2*)&sVh[r * STR_ + c4] = hh;
            *(uint2*)&sVl[r * STR_ + c4] = ll;
        }
        __syncthreads();

        // ---- S = Q @ K^T (split 3-term) ----
        float sc[8][4];
#pragma unroll
        for (int nt = 0; nt < 8; nt++)
#pragma unroll
            for (int e = 0; e < 4; e++) sc[nt][e] = 0.0f;
#pragma unroll
        for (int k = 0; k < 4; k++) {
#pragma unroll
            for (int nt = 0; nt < 8; nt++) {
                uint32_t bh[2], bl[2];
                const int boff = (nt * 8 + kr) * STR_ + kc + k * 16;
                ldsm_x2(bh[0], bh[1], smem_u32(&sKh[boff]));
                ldsm_x2(bl[0], bl[1], smem_u32(&sKl[boff]));
                mma16816(sc[nt], aqh[k], bh);
                mma16816(sc[nt], aqh[k], bl);
                mma16816(sc[nt], aql[k], bh);
            }
        }

        // ---- online softmax (rows g, g+8 of this warp's 16-row group) ----
        float mx0 = -1e30f, mx1 = -1e30f;
#pragma unroll
        for (int nt = 0; nt < 8; nt++) {
            mx0 = fmaxf(mx0, fmaxf(sc[nt][0], sc[nt][1]));
            mx1 = fmaxf(mx1, fmaxf(sc[nt][2], sc[nt][3]));
        }
        mx0 = fmaxf(mx0, __shfl_xor_sync(0xffffffffu, mx0, 1));
        mx0 = fmaxf(mx0, __shfl_xor_sync(0xffffffffu, mx0, 2));
        mx1 = fmaxf(mx1, __shfl_xor_sync(0xffffffffu, mx1, 1));
        mx1 = fmaxf(mx1, __shfl_xor_sync(0xffffffffu, mx1, 2));
        const float mn0 = fmaxf(m0, mx0), mn1 = fmaxf(m1, mx1);
        const float c0 = __expf(m0 - mn0), c1 = __expf(m1 - mn1);
        float rs0 = 0.0f, rs1 = 0.0f;
#pragma unroll
        for (int nt = 0; nt < 8; nt++) {
            sc[nt][0] = __expf(sc[nt][0] - mn0);
            sc[nt][1] = __expf(sc[nt][1] - mn0);
            sc[nt][2] = __expf(sc[nt][2] - mn1);
            sc[nt][3] = __expf(sc[nt][3] - mn1);
            rs0 += sc[nt][0] + sc[nt][1];
            rs1 += sc[nt][2] + sc[nt][3];
        }
        rs0 += __shfl_xor_sync(0xffffffffu, rs0, 1);
        rs0 += __shfl_xor_sync(0xffffffffu, rs0, 2);
        rs1 += __shfl_xor_sync(0xffffffffu, rs1, 1);
        rs1 += __shfl_xor_sync(0xffffffffu, rs1, 2);
        l0 = l0 * c0 + rs0;
        l1 = l1 * c1 + rs1;
        m0 = mn0; m1 = mn1;
#pragma unroll
        for (int dt = 0; dt < 8; dt++) {
            o[dt][0] *= c0; o[dt][1] *= c0;
            o[dt][2] *= c1; o[dt][3] *= c1;
        }

        // ---- O += P @ V (split 3-term); P from registers, V via ldsm.trans ----
#pragma unroll
        for (int kq = 0; kq < 4; kq++) {
            uint32_t ph[4], pl[4];
            ph[0] = pack_hi2(sc[2 * kq][0], sc[2 * kq][1]);
            ph[1] = pack_hi2(sc[2 * kq][2], sc[2 * kq][3]);
            ph[2] = pack_hi2(sc[2 * kq + 1][0], sc[2 * kq + 1][1]);
            ph[3] = pack_hi2(sc[2 * kq + 1][2], sc[2 * kq + 1][3]);
            pl[0] = pack_lo2(sc[2 * kq][0], sc[2 * kq][1]);
            pl[1] = pack_lo2(sc[2 * kq][2], sc[2 * kq][3]);
            pl[2] = pack_lo2(sc[2 * kq + 1][0], sc[2 * kq + 1][1]);
            pl[3] = pack_lo2(sc[2 * kq + 1][2], sc[2 * kq + 1][3]);
#pragma unroll
            for (int dt = 0; dt < 8; dt++) {
                uint32_t bvh[2], bvl[2];
                const int voff = (kq * 16 + vr) * STR_ + dt * 8;
                ldsm_x2_t(bvh[0], bvh[1], smem_u32(&sVh[voff]));
                ldsm_x2_t(bvl[0], bvl[1], smem_u32(&sVl[voff]));
                mma16816(o[dt], ph, bvh);
                mma16816(o[dt], ph, bvl);
                mma16816(o[dt], pl, bvh);
            }
        }
    }

    // ---- epilogue: normalize, write [B,S,D] ----
    const float inv0 = 1.0f / l0, inv1 = 1.0f / l1;
    const int r0 = qt * 64 + w * 16 + g;
    const int r1 = r0 + 8;
#pragma unroll
    for (int dt = 0; dt < 8; dt++) {
        const int d0 = h * 64 + dt * 8 + t * 2;
        *(float2*)&out[(size_t)(b * S_ + r0) * 1024 + d0] =
            make_float2(o[dt][0] * inv0, o[dt][1] * inv0);
        *(float2*)&out[(size_t)(b * S_ + r1) * 1024 + d0] =
            make_float2(o[dt][2] * inv1, o[dt][3] * inv1);
    }
}

// ---------------------------------------------------------------------------
extern "C" void kernel_launch(void* const* d_in, const int* in_sizes, int n_in,
                              void* d_out, int out_size)
{
    const float* x      = (const float*)d_in[0];
    const float* qkv_w  = (const float*)d_in[1];
    const float* qkv_b  = (const float*)d_in[2];
    const float* out_w  = (const float*)d_in[3];
    const float* out_b  = (const float*)d_in[4];
    const float* akmin  = (const float*)d_in[5];
    const float* akmax  = (const float*)d_in[6];
    const float* avmin  = (const float*)d_in[7];
    const float* avmax  = (const float*)d_in[8];
    float* out = (float*)d_out;

    float *qkv_buf = nullptr, *attn_buf = nullptr;
    __nv_bfloat16 *ah, *al, *wqh, *wql, *woh, *wol;
    cudaGetSymbolAddress((void**)&qkv_buf, g_qkv);
    cudaGetSymbolAddress((void**)&attn_buf, g_attn);
    cudaGetSymbolAddress((void**)&ah,  g_ah);
    cudaGetSymbolAddress((void**)&al,  g_al);
    cudaGetSymbolAddress((void**)&wqh, g_wqh);
    cudaGetSymbolAddress((void**)&wql, g_wql);
    cudaGetSymbolAddress((void**)&woh, g_woh);
    cudaGetSymbolAddress((void**)&wol, g_wol);

    const int attn_smem = 6 * 64 * STR_ * (int)sizeof(__nv_bfloat16);  // 55296
    cudaFuncSetAttribute(attn_tc_kernel, cudaFuncAttributeMaxDynamicSharedMemorySize,
                         attn_smem);

    // 0) split fp32 -> hi/lo bf16
    split_kernel<<<(M_ROWS * D_ / 4 + 255) / 256, 256>>>(x, ah, al, M_ROWS * D_ / 4);
    split_kernel<<<(N_QKV * D_ / 4 + 255) / 256, 256>>>(qkv_w, wqh, wql, N_QKV * D_ / 4);
    split_kernel<<<(D_ * D_ / 4 + 255) / 256, 256>>>(out_w, woh, wol, D_ * D_ / 4);

    // 1) QKV projection + bias + guard-clamp (tensor cores)
    {
        dim3 grid(N_QKV / 128, M_ROWS / 128);
        gemm_bf16s_kernel<true><<<grid, 256>>>(
            ah, al, wqh, wql, qkv_b, qkv_buf, M_ROWS, N_QKV, D_,
            akmin, akmax, avmin, avmax);
    }

    // 2) Tensor-core flash attention
    {
        dim3 grid(S_ / 64, H_, B_);
        attn_tc_kernel<<<grid, 128, attn_smem>>>(qkv_buf, attn_buf);
    }

    // 3) split attention output, then output projection
    split_kernel<<<(M_ROWS * D_ / 4 + 255) / 256, 256>>>(attn_buf, ah, al, M_ROWS * D_ / 4);
    {
        dim3 grid(D_ / 128, M_ROWS / 128);
        gemm_bf16s_kernel<false><<<grid, 256>>>(
            ah, al, woh, wol, out_b, out, M_ROWS, D_, D_,
            nullptr, nullptr, nullptr, nullptr);
    }
}

// round 5
// speedup vs baseline: 2.6816x; 1.1043x over previous
#include <cuda_runtime.h>
#include <cuda_bf16.h>
#include <cstdint>

#define B_   2
#define S_   2048
#define D_   1024
#define H_   16
#define DK_  64
#define EPS_ 0.1f
#define M_ROWS (B_ * S_)          // 4096
#define N_QKV  (3 * D_)           // 3072

// Scratch (allocation-free requirement -> __device__ globals)
__device__ __nv_bfloat16 g_qkvh[M_ROWS * N_QKV];  // split-hi of clamped/scaled QKV
__device__ __nv_bfloat16 g_qkvl[M_ROWS * N_QKV];  // split-lo
__device__ __nv_bfloat16 g_ah[M_ROWS * D_];       // split-hi of A operand (x, then attn out)
__device__ __nv_bfloat16 g_al[M_ROWS * D_];
__device__ __nv_bfloat16 g_wqh[N_QKV * D_];
__device__ __nv_bfloat16 g_wql[N_QKV * D_];
__device__ __nv_bfloat16 g_woh[D_ * D_];
__device__ __nv_bfloat16 g_wol[D_ * D_];

// ---------------------------------------------------------------------------
// helpers
// ---------------------------------------------------------------------------
__device__ __forceinline__ uint32_t smem_u32(const void* p) {
    return (uint32_t)__cvta_generic_to_shared(p);
}
__device__ __forceinline__ void ldsm_x4(uint32_t& r0, uint32_t& r1, uint32_t& r2,
                                        uint32_t& r3, uint32_t addr) {
    asm volatile("ldmatrix.sync.aligned.m8n8.x4.shared.b16 {%0,%1,%2,%3}, [%4];"
                 : "=r"(r0), "=r"(r1), "=r"(r2), "=r"(r3) : "r"(addr));
}
__device__ __forceinline__ void ldsm_x2(uint32_t& r0, uint32_t& r1, uint32_t addr) {
    asm volatile("ldmatrix.sync.aligned.m8n8.x2.shared.b16 {%0,%1}, [%2];"
                 : "=r"(r0), "=r"(r1) : "r"(addr));
}
__device__ __forceinline__ void ldsm_x2_t(uint32_t& r0, uint32_t& r1, uint32_t addr) {
    asm volatile("ldmatrix.sync.aligned.m8n8.x2.trans.shared.b16 {%0,%1}, [%2];"
                 : "=r"(r0), "=r"(r1) : "r"(addr));
}
__device__ __forceinline__ void mma16816(float c[4], const uint32_t a[4],
                                         const uint32_t b[2]) {
    asm volatile(
        "mma.sync.aligned.m16n8k16.row.col.f32.bf16.bf16.f32 "
        "{%0,%1,%2,%3}, {%4,%5,%6,%7}, {%8,%9}, {%0,%1,%2,%3};"
        : "+f"(c[0]), "+f"(c[1]), "+f"(c[2]), "+f"(c[3])
        : "r"(a[0]), "r"(a[1]), "r"(a[2]), "r"(a[3]), "r"(b[0]), "r"(b[1]));
}
__device__ __forceinline__ uint32_t pack_hi2(float x, float y) {
    __nv_bfloat162 t = __floats2bfloat162_rn(x, y);
    return *(uint32_t*)&t;
}
__device__ __forceinline__ uint32_t pack_lo2(float x, float y) {
    float hx = __bfloat162float(__float2bfloat16(x));
    float hy = __bfloat162float(__float2bfloat16(y));
    __nv_bfloat162 t = __floats2bfloat162_rn(x - hx, y - hy);
    return *(uint32_t*)&t;
}
__device__ __forceinline__ void cpasync16(uint32_t saddr, const void* g) {
    asm volatile("cp.async.ca.shared.global [%0], [%1], 16;" :: "r"(saddr), "l"(g));
}
__device__ __forceinline__ void cpcommit() {
    asm volatile("cp.async.commit_group;");
}
template <int N>
__device__ __forceinline__ void cpwait() {
    asm volatile("cp.async.wait_group %0;" :: "n"(N));
}

// ---------------------------------------------------------------------------
// fp32 -> (hi,lo) bf16 split
// ---------------------------------------------------------------------------
__global__ void split_kernel(const float* __restrict__ in,
                             __nv_bfloat16* __restrict__ hi,
                             __nv_bfloat16* __restrict__ lo, int n4) {
    int i = blockIdx.x * blockDim.x + threadIdx.x;
    if (i >= n4) return;
    float4 f = ((const float4*)in)[i];
    uint2 hh, ll;
    hh.x = pack_hi2(f.x, f.y); hh.y = pack_hi2(f.z, f.w);
    ll.x = pack_lo2(f.x, f.y); ll.y = pack_lo2(f.z, f.w);
    ((uint2*)hi)[i] = hh;
    ((uint2*)lo)[i] = ll;
}

// ---------------------------------------------------------------------------
// guard clamp (QKV epilogue)
// ---------------------------------------------------------------------------
__device__ __forceinline__ float guard_clamp(
    float v, int m, int n,
    const float* __restrict__ akmin, const float* __restrict__ akmax,
    const float* __restrict__ avmin, const float* __restrict__ avmax) {
    const int c = n >> 10;                 // 1=k, 2=v (caller handles c==0)
    const int b  = m >> 11;
    const int h  = (n & 1023) >> 6;
    const int ch = n & 63;
    const int ai = ((b << 4) + h) * 64 + ch;
    const float amin = (c == 1) ? akmin[ai] : avmin[ai];
    const float amax = (c == 1) ? akmax[ai] : avmax[ai];
    float lo = fmaxf(v - EPS_, amin);
    float hi = fminf(v + EPS_, amax);
    lo = fminf(lo, hi);
    return fmaxf(lo, fminf(v, hi));
}

// ---------------------------------------------------------------------------
// Split-bf16 tensor-core GEMM:  C = A @ B^T + bias.
// 3-stage cp.async ring, one __syncthreads per k-step.
// MODE 0: fp32 output (out projection).  MODE 1: split-bf16 QKV output with
// Q-scaling (x 1/8, exact) and guard-clamp of K/V.
// Block 128x128, BK=16, 256 thr = 8 warps (2 M x 4 N), warp tile 64x32.
// ---------------------------------------------------------------------------
#define GSTG 12288   // bf16 elements per pipeline stage (4 arrays x 128 x 24)

template <int MODE>
__global__ __launch_bounds__(256) void gemm_bf16s_kernel(
    const __nv_bfloat16* __restrict__ Ah, const __nv_bfloat16* __restrict__ Al,
    const __nv_bfloat16* __restrict__ Bh, const __nv_bfloat16* __restrict__ Bl,
    const float* __restrict__ bias,
    float* __restrict__ C,
    __nv_bfloat16* __restrict__ Ch, __nv_bfloat16* __restrict__ Cl,
    int M, int N, int K,
    const float* __restrict__ akmin, const float* __restrict__ akmax,
    const float* __restrict__ avmin, const float* __restrict__ avmax)
{
    extern __shared__ __nv_bfloat16 smem[];

    const int tid  = threadIdx.x;
    const int wid  = tid >> 5;
    const int lane = tid & 31;
    const int warp_m = (wid & 1) * 64;
    const int warp_n = (wid >> 1) * 32;
    const int bm = blockIdx.y * 128;
    const int bn = blockIdx.x * 128;

    const int row = tid >> 1;
    const int ko  = (tid & 1) * 8;
    const int so  = row * 24 + ko;       // smem element offset within array
    const __nv_bfloat16* gAh = Ah + (size_t)(bm + row) * K + ko;
    const __nv_bfloat16* gAl = Al + (size_t)(bm + row) * K + ko;
    const __nv_bfloat16* gBh = Bh + (size_t)(bn + row) * K + ko;
    const __nv_bfloat16* gBl = Bl + (size_t)(bn + row) * K + ko;

    float c[4][4][4];
#pragma unroll
    for (int mt = 0; mt < 4; mt++)
#pragma unroll
        for (int nt = 0; nt < 4; nt++)
#pragma unroll
            for (int e = 0; e < 4; e++) c[mt][nt][e] = 0.0f;

    const int KS = K >> 4;

    // prologue: stages 0,1
#pragma unroll
    for (int p = 0; p < 2; p++) {
        __nv_bfloat16* st = smem + p * GSTG;
        const int off = p * 16;
        cpasync16(smem_u32(st + so),        gAh + off);
        cpasync16(smem_u32(st + 3072 + so), gAl + off);
        cpasync16(smem_u32(st + 6144 + so), gBh + off);
        cpasync16(smem_u32(st + 9216 + so), gBl + off);
        cpcommit();
    }

    const int ar = lane & 15, ac = (lane >> 4) << 3;
    const int br = lane & 7,  bc = ((lane >> 3) & 1) << 3;

    int stage_c = 0;   // compute stage
    int stage_i = 2;   // issue target stage
    for (int ks = 0; ks < KS; ks++) {
        if (ks + 1 < KS) cpwait<1>(); else cpwait<0>();
        __syncthreads();
        const __nv_bfloat16* sb = smem + stage_c * GSTG;

        uint32_t afh[4][4], afl[4][4], bfh[4][2], bfl[4][2];
#pragma unroll
        for (int mt = 0; mt < 4; mt++) {
            const int r = (warp_m + mt * 16 + ar) * 24 + ac;
            ldsm_x4(afh[mt][0], afh[mt][1], afh[mt][2], afh[mt][3],
                    smem_u32(sb + r));
            ldsm_x4(afl[mt][0], afl[mt][1], afl[mt][2], afl[mt][3],
                    smem_u32(sb + 3072 + r));
        }
#pragma unroll
        for (int nt = 0; nt < 4; nt++) {
            const int r = (warp_n + nt * 8 + br) * 24 + bc;
            ldsm_x2(bfh[nt][0], bfh[nt][1], smem_u32(sb + 6144 + r));
            ldsm_x2(bfl[nt][0], bfl[nt][1], smem_u32(sb + 9216 + r));
        }
#pragma unroll
        for (int mt = 0; mt < 4; mt++)
#pragma unroll
            for (int nt = 0; nt < 4; nt++) {
                mma16816(c[mt][nt], afh[mt], bfh[nt]);
                mma16816(c[mt][nt], afh[mt], bfl[nt]);
                mma16816(c[mt][nt], afl[mt], bfh[nt]);
            }

        if (ks + 2 < KS) {
            __nv_bfloat16* st = smem + stage_i * GSTG;
            const int off = (ks + 2) * 16;
            cpasync16(smem_u32(st + so),        gAh + off);
            cpasync16(smem_u32(st + 3072 + so), gAl + off);
            cpasync16(smem_u32(st + 6144 + so), gBh + off);
            cpasync16(smem_u32(st + 9216 + so), gBl + off);
            cpcommit();
        }
        stage_c = (stage_c == 2) ? 0 : stage_c + 1;
        stage_i = (stage_i == 2) ? 0 : stage_i + 1;
    }

    // Epilogue
    const int g = lane >> 2, t = lane & 3;
#pragma unroll
    for (int mt = 0; mt < 4; mt++) {
#pragma unroll
        for (int nt = 0; nt < 4; nt++) {
            const int n0 = bn + warp_n + nt * 8 + t * 2;
            const float b0 = bias[n0], b1 = bias[n0 + 1];
#pragma unroll
            for (int half = 0; half < 2; half++) {
                const int m = bm + warp_m + mt * 16 + g + half * 8;
                float v0 = c[mt][nt][half * 2 + 0] + b0;
                float v1 = c[mt][nt][half * 2 + 1] + b1;
                if (MODE == 1) {
                    if ((n0 >> 10) == 0) {          // q channels: pre-scale
                        v0 *= 0.125f; v1 *= 0.125f;
                    } else {                         // k/v: guard-clamp
                        v0 = guard_clamp(v0, m, n0,     akmin, akmax, avmin, avmax);
                        v1 = guard_clamp(v1, m, n0 + 1, akmin, akmax, avmin, avmax);
                    }
                    const uint32_t hh = pack_hi2(v0, v1);
                    const uint32_t ll = pack_lo2(v0, v1);
                    *(uint32_t*)&Ch[(size_t)m * N + n0] = hh;
                    *(uint32_t*)&Cl[(size_t)m * N + n0] = ll;
                } else {
                    *(float2*)&C[(size_t)m * N + n0] = make_float2(v0, v1);
                }
            }
        }
    }
}

// ---------------------------------------------------------------------------
// Tensor-core flash attention over pre-split bf16 QKV (no conversion inside).
// Block = (b,h, 64-row Q tile), 128 threads = 4 warps, warp owns 16 q-rows.
// smem: Qh,Ql,Kh,Kl,Vh,Vl each [64][72] bf16 = 55296 B dynamic.
// Epilogue writes split-bf16 output (A-operand of the out projection).
// ---------------------------------------------------------------------------
#define STR_ 72

__global__ __launch_bounds__(128) void attn_tc_kernel(
    const __nv_bfloat16* __restrict__ qkvh,
    const __nv_bfloat16* __restrict__ qkvl,
    __nv_bfloat16* __restrict__ oh, __nv_bfloat16* __restrict__ ol)
{
    extern __shared__ __nv_bfloat16 sb[];
    __nv_bfloat16* sQh = sb;
    __nv_bfloat16* sQl = sQh + 64 * STR_;
    __nv_bfloat16* sKh = sQl + 64 * STR_;
    __nv_bfloat16* sKl = sKh + 64 * STR_;
    __nv_bfloat16* sVh = sKl + 64 * STR_;
    __nv_bfloat16* sVl = sVh + 64 * STR_;

    const int qt = blockIdx.x, h = blockIdx.y, b = blockIdx.z;
    const int tid = threadIdx.x, w = tid >> 5, lane = tid & 31;
    const int g = lane >> 2, t = lane & 3;

    // ---- load Q tile (already scaled + split by GEMM1) ----
#pragma unroll
    for (int it = 0; it < 4; it++) {
        const int idx = tid + it * 128;          // 0..511 uint4 chunks
        const int r = idx >> 3, c8 = (idx & 7) << 3;
        const size_t gb = ((size_t)(b * S_ + qt * 64 + r) * 3) * 1024 + h * 64 + c8;
        *(uint4*)&sQh[r * STR_ + c8] = *(const uint4*)(qkvh + gb);
        *(uint4*)&sQl[r * STR_ + c8] = *(const uint4*)(qkvl + gb);
    }
    __syncthreads();

    // ---- hoist Q fragments (4 k-steps) ----
    uint32_t aqh[4][4], aql[4][4];
    const int ar = lane & 15, ac8 = (lane >> 4) << 3;
#pragma unroll
    for (int k = 0; k < 4; k++) {
        const int roff = (w * 16 + ar) * STR_ + ac8 + k * 16;
        ldsm_x4(aqh[k][0], aqh[k][1], aqh[k][2], aqh[k][3], smem_u32(&sQh[roff]));
        ldsm_x4(aql[k][0], aql[k][1], aql[k][2], aql[k][3], smem_u32(&sQl[roff]));
    }

    float o[8][4];
#pragma unroll
    for (int dt = 0; dt < 8; dt++)
#pragma unroll
        for (int e = 0; e < 4; e++) o[dt][e] = 0.0f;
    float m0 = -1e30f, m1 = -1e30f, l0 = 0.0f, l1 = 0.0f;

    const int kr = lane & 7, kc = ((lane >> 3) & 1) << 3;
    const int vr = lane & 15;

    for (int kt = 0; kt < S_ / 64; kt++) {
        __syncthreads();
        // ---- load K,V tiles (pure copies, no conversion) ----
#pragma unroll
        for (int it = 0; it < 4; it++) {
            const int idx = tid + it * 128;
            const int r = idx >> 3, c8 = (idx & 7) << 3;
            const size_t gb =
                ((size_t)(b * S_ + kt * 64 + r) * 3) * 1024 + h * 64 + c8;
            *(uint4*)&sKh[r * STR_ + c8] = *(const uint4*)(qkvh + gb + 1024);
            *(uint4*)&sKl[r * STR_ + c8] = *(const uint4*)(qkvl + gb + 1024);
            *(uint4*)&sVh[r * STR_ + c8] = *(const uint4*)(qkvh + gb + 2048);
            *(uint4*)&sVl[r * STR_ + c8] = *(const uint4*)(qkvl + gb + 2048);
        }
        __syncthreads();

        // ---- S = Q @ K^T (split 3-term) ----
        float sc[8][4];
#pragma unroll
        for (int nt = 0; nt < 8; nt++)
#pragma unroll
            for (int e = 0; e < 4; e++) sc[nt][e] = 0.0f;
#pragma unroll
        for (int k = 0; k < 4; k++) {
#pragma unroll
            for (int nt = 0; nt < 8; nt++) {
                uint32_t bh[2], bl[2];
                const int boff = (nt * 8 + kr) * STR_ + kc + k * 16;
                ldsm_x2(bh[0], bh[1], smem_u32(&sKh[boff]));
                ldsm_x2(bl[0], bl[1], smem_u32(&sKl[boff]));
                mma16816(sc[nt], aqh[k], bh);
                mma16816(sc[nt], aqh[k], bl);
                mma16816(sc[nt], aql[k], bh);
            }
        }

        // ---- online softmax (rows g, g+8 of this warp's 16-row group) ----
        float mx0 = -1e30f, mx1 = -1e30f;
#pragma unroll
        for (int nt = 0; nt < 8; nt++) {
            mx0 = fmaxf(mx0, fmaxf(sc[nt][0], sc[nt][1]));
            mx1 = fmaxf(mx1, fmaxf(sc[nt][2], sc[nt][3]));
        }
        mx0 = fmaxf(mx0, __shfl_xor_sync(0xffffffffu, mx0, 1));
        mx0 = fmaxf(mx0, __shfl_xor_sync(0xffffffffu, mx0, 2));
        mx1 = fmaxf(mx1, __shfl_xor_sync(0xffffffffu, mx1, 1));
        mx1 = fmaxf(mx1, __shfl_xor_sync(0xffffffffu, mx1, 2));
        const float mn0 = fmaxf(m0, mx0), mn1 = fmaxf(m1, mx1);
        const float c0 = __expf(m0 - mn0), c1 = __expf(m1 - mn1);
        float rs0 = 0.0f, rs1 = 0.0f;
#pragma unroll
        for (int nt = 0; nt < 8; nt++) {
            sc[nt][0] = __expf(sc[nt][0] - mn0);
            sc[nt][1] = __expf(sc[nt][1] - mn0);
            sc[nt][2] = __expf(sc[nt][2] - mn1);
            sc[nt][3] = __expf(sc[nt][3] - mn1);
            rs0 += sc[nt][0] + sc[nt][1];
            rs1 += sc[nt][2] + sc[nt][3];
        }
        rs0 += __shfl_xor_sync(0xffffffffu, rs0, 1);
        rs0 += __shfl_xor_sync(0xffffffffu, rs0, 2);
        rs1 += __shfl_xor_sync(0xffffffffu, rs1, 1);
        rs1 += __shfl_xor_sync(0xffffffffu, rs1, 2);
        l0 = l0 * c0 + rs0;
        l1 = l1 * c1 + rs1;
        m0 = mn0; m1 = mn1;
#pragma unroll
        for (int dt = 0; dt < 8; dt++) {
            o[dt][0] *= c0; o[dt][1] *= c0;
            o[dt][2] *= c1; o[dt][3] *= c1;
        }

        // ---- O += P @ V (split 3-term); P from registers, V via ldsm.trans ----
#pragma unroll
        for (int kq = 0; kq < 4; kq++) {
            uint32_t ph[4], pl[4];
            ph[0] = pack_hi2(sc[2 * kq][0], sc[2 * kq][1]);
            ph[1] = pack_hi2(sc[2 * kq][2], sc[2 * kq][3]);
            ph[2] = pack_hi2(sc[2 * kq + 1][0], sc[2 * kq + 1][1]);
            ph[3] = pack_hi2(sc[2 * kq + 1][2], sc[2 * kq + 1][3]);
            pl[0] = pack_lo2(sc[2 * kq][0], sc[2 * kq][1]);
            pl[1] = pack_lo2(sc[2 * kq][2], sc[2 * kq][3]);
            pl[2] = pack_lo2(sc[2 * kq + 1][0], sc[2 * kq + 1][1]);
            pl[3] = pack_lo2(sc[2 * kq + 1][2], sc[2 * kq + 1][3]);
#pragma unroll
            for (int dt = 0; dt < 8; dt++) {
                uint32_t bvh[2], bvl[2];
                const int voff = (kq * 16 + vr) * STR_ + dt * 8;
                ldsm_x2_t(bvh[0], bvh[1], smem_u32(&sVh[voff]));
                ldsm_x2_t(bvl[0], bvl[1], smem_u32(&sVl[voff]));
                mma16816(o[dt], ph, bvh);
                mma16816(o[dt], ph, bvl);
                mma16816(o[dt], pl, bvh);
            }
        }
    }

    // ---- epilogue: normalize, split to bf16 hi/lo, write [B,S,D] ----
    const float inv0 = 1.0f / l0, inv1 = 1.0f / l1;
    const int r0 = qt * 64 + w * 16 + g;
    const int r1 = r0 + 8;
#pragma unroll
    for (int dt = 0; dt < 8; dt++) {
        const int d0 = h * 64 + dt * 8 + t * 2;
        const float x0 = o[dt][0] * inv0, x1 = o[dt][1] * inv0;
        const float y0 = o[dt][2] * inv1, y1 = o[dt][3] * inv1;
        const size_t p0 = (size_t)(b * S_ + r0) * 1024 + d0;
        const size_t p1 = (size_t)(b * S_ + r1) * 1024 + d0;
        *(uint32_t*)&oh[p0] = pack_hi2(x0, x1);
        *(uint32_t*)&ol[p0] = pack_lo2(x0, x1);
        *(uint32_t*)&oh[p1] = pack_hi2(y0, y1);
        *(uint32_t*)&ol[p1] = pack_lo2(y0, y1);
    }
}

// ---------------------------------------------------------------------------
extern "C" void kernel_launch(void* const* d_in, const int* in_sizes, int n_in,
                              void* d_out, int out_size)
{
    const float* x      = (const float*)d_in[0];
    const float* qkv_w  = (const float*)d_in[1];
    const float* qkv_b  = (const float*)d_in[2];
    const float* out_w  = (const float*)d_in[3];
    const float* out_b  = (const float*)d_in[4];
    const float* akmin  = (const float*)d_in[5];
    const float* akmax  = (const float*)d_in[6];
    const float* avmin  = (const float*)d_in[7];
    const float* avmax  = (const float*)d_in[8];
    float* out = (float*)d_out;

    __nv_bfloat16 *qkvh, *qkvl, *ah, *al, *wqh, *wql, *woh, *wol;
    cudaGetSymbolAddress((void**)&qkvh, g_qkvh);
    cudaGetSymbolAddress((void**)&qkvl, g_qkvl);
    cudaGetSymbolAddress((void**)&ah,  g_ah);
    cudaGetSymbolAddress((void**)&al,  g_al);
    cudaGetSymbolAddress((void**)&wqh, g_wqh);
    cudaGetSymbolAddress((void**)&wql, g_wql);
    cudaGetSymbolAddress((void**)&woh, g_woh);
    cudaGetSymbolAddress((void**)&wol, g_wol);

    const int gemm_smem = 3 * GSTG * (int)sizeof(__nv_bfloat16);            // 73728
    const int attn_smem = 6 * 64 * STR_ * (int)sizeof(__nv_bfloat16);       // 55296
    cudaFuncSetAttribute(gemm_bf16s_kernel<1>,
                         cudaFuncAttributeMaxDynamicSharedMemorySize, gemm_smem);
    cudaFuncSetAttribute(gemm_bf16s_kernel<0>,
                         cudaFuncAttributeMaxDynamicSharedMemorySize, gemm_smem);
    cudaFuncSetAttribute(attn_tc_kernel,
                         cudaFuncAttributeMaxDynamicSharedMemorySize, attn_smem);

    // 0) split fp32 inputs -> hi/lo bf16
    split_kernel<<<(M_ROWS * D_ / 4 + 255) / 256, 256>>>(x, ah, al, M_ROWS * D_ / 4);
    split_kernel<<<(N_QKV * D_ / 4 + 255) / 256, 256>>>(qkv_w, wqh, wql, N_QKV * D_ / 4);
    split_kernel<<<(D_ * D_ / 4 + 255) / 256, 256>>>(out_w, woh, wol, D_ * D_ / 4);

    // 1) QKV projection + bias + q-scale + guard-clamp -> split bf16 QKV
    {
        dim3 grid(N_QKV / 128, M_ROWS / 128);
        gemm_bf16s_kernel<1><<<grid, 256, gemm_smem>>>(
            ah, al, wqh, wql, qkv_b, nullptr, qkvh, qkvl, M_ROWS, N_QKV, D_,
            akmin, akmax, avmin, avmax);
    }

    // 2) Tensor-core flash attention (writes split-bf16 output into ah/al)
    {
        dim3 grid(S_ / 64, H_, B_);
        attn_tc_kernel<<<grid, 128, attn_smem>>>(qkvh, qkvl, ah, al);
    }

    // 3) Output projection (fp32 result)
    {
        dim3 grid(D_ / 128, M_ROWS / 128);
        gemm_bf16s_kernel<0><<<grid, 256, gemm_smem>>>(
            ah, al, woh, wol, out_b, out, nullptr, nullptr, M_ROWS, D_, D_,
            nullptr, nullptr, nullptr, nullptr);
    }
}